// round 6
// baseline (speedup 1.0000x reference)
#include <cuda_runtime.h>
#include <cuda_fp16.h>

// ---------------------------------------------------------------------------
// 3-layer GCN. R6: GEMMs switched from tf32 3x-split (conversion-bound) to
// fp16 3x-split mma.m16n8k16 with the hi/lo split done ONCE per tile into
// smem (Ah/Al, Wh/Wl with W transposed n-major). Inner loop is pure
// LDS.32 + HMMA. Agg (fp16 gathers) and CSR preproc unchanged.
// ---------------------------------------------------------------------------

#define NN 100000
#define NE 1600000
#define IN_C 256
#define H1C 128
#define H2C 64
#define OUTC 32

__device__ int    g_cnt[NN];
__device__ int    g_cursor[NN];
__device__ int    g_off[NN];
__device__ int    g_bsum[128];
__device__ int    g_boff[128];
__device__ float  g_dis[NN];
__device__ int    g_esrc[NE];
__device__ float  g_enorm[NE];
__device__ __half g_h[(size_t)NN * 128];   // transformed features, fp16
__device__ float4 g_a4[(size_t)NN * 32];   // aggregated features, fp32

// ---------------------------------------------------------------------------
// graph preprocessing
// ---------------------------------------------------------------------------
__global__ void k_zero(int n) {
    int i = blockIdx.x * blockDim.x + threadIdx.x;
    if (i < n) { g_cnt[i] = 0; g_cursor[i] = 0; }
}

__global__ void k_count(const int* __restrict__ col, int e_cnt) {
    int e = blockIdx.x * blockDim.x + threadIdx.x;
    if (e < e_cnt) atomicAdd(&g_cnt[col[e]], 1);
}

__global__ void k_dis(int n) {
    int i = blockIdx.x * blockDim.x + threadIdx.x;
    if (i < n) g_dis[i] = rsqrtf((float)g_cnt[i] + 1.0f);
}

__global__ void k_scan1(int n) {
    __shared__ int s[1024];
    int i = blockIdx.x * 1024 + threadIdx.x;
    int v = (i < n) ? g_cnt[i] : 0;
    s[threadIdx.x] = v;
    __syncthreads();
    #pragma unroll
    for (int off = 1; off < 1024; off <<= 1) {
        int t = (threadIdx.x >= off) ? s[threadIdx.x - off] : 0;
        __syncthreads();
        s[threadIdx.x] += t;
        __syncthreads();
    }
    if (i < n) g_off[i] = s[threadIdx.x];
    if (threadIdx.x == 1023) g_bsum[blockIdx.x] = s[1023];
}

__global__ void k_scan2(int nb) {
    if (blockIdx.x == 0 && threadIdx.x == 0) {
        int run = 0;
        for (int b = 0; b < nb; b++) { g_boff[b] = run; run += g_bsum[b]; }
    }
}

__global__ void k_scan3(int n) {
    int i = blockIdx.x * blockDim.x + threadIdx.x;
    if (i < n) g_off[i] = g_off[i] - g_cnt[i] + g_boff[i >> 10];
}

__global__ void k_scatter(const int* __restrict__ row, const int* __restrict__ col, int e_cnt) {
    int e = blockIdx.x * blockDim.x + threadIdx.x;
    if (e >= e_cnt) return;
    int r = row[e], c = col[e];
    int pos = g_off[c] + atomicAdd(&g_cursor[c], 1);
    g_esrc[pos]  = r;
    g_enorm[pos] = g_dis[r] * g_dis[c];
}

// ---------------------------------------------------------------------------
// fp16 3x-split tensor-core GEMM:  C[M,N] = A[M,K] @ W[K,N], fp16 output
// ---------------------------------------------------------------------------
__device__ __forceinline__ void mma_f16(float* c, const unsigned* a, const unsigned* b) {
    asm volatile(
        "mma.sync.aligned.m16n8k16.row.col.f32.f16.f16.f32 "
        "{%0,%1,%2,%3},{%4,%5,%6,%7},{%8,%9},{%0,%1,%2,%3};"
        : "+f"(c[0]), "+f"(c[1]), "+f"(c[2]), "+f"(c[3])
        : "r"(a[0]), "r"(a[1]), "r"(a[2]), "r"(a[3]), "r"(b[0]), "r"(b[1]));
}

__device__ __forceinline__ void split2(float v, __half& hi, __half& lo) {
    hi = __float2half_rn(v);
    lo = __float2half_rn(v - __half2float(hi));
}

template <int N, int K>
__launch_bounds__(256)
__global__ void k_gemm_f16(const float* __restrict__ A, const float* __restrict__ W,
                           __half* __restrict__ C, int M) {
    constexpr int BM = 128, BK = 32;
    constexpr int S = BK + 8;          // half stride: 40 -> conflict-free frags
    constexpr int WARPS_M = 4, WARPS_N = 2;
    constexpr int WM = BM / WARPS_M;   // 32
    constexpr int WN = N / WARPS_N;    // 64 / 32 / 16
    constexpr int MT = WM / 16;        // 2
    constexpr int NT = WN / 8;         // 8 / 4 / 2

    __shared__ __half Ah[BM * S], Al[BM * S];
    __shared__ __half Wh[N * S],  Wl[N * S];

    int tid = threadIdx.x;
    int lane = tid & 31, warp = tid >> 5;
    int wm = (warp % WARPS_M) * WM;
    int wn = (warp / WARPS_M) * WN;
    int m0 = blockIdx.x * BM;
    int g = lane >> 2, tg = lane & 3;

    float acc[MT][NT][4] = {};

    for (int k0 = 0; k0 < K; k0 += BK) {
        // ---- A tile: 128x32 fp32, split to Ah/Al[row][k] ----
        #pragma unroll
        for (int i = 0; i < 4; i++) {
            int idx = tid + i * 256;
            int r = idx >> 3, c4 = idx & 7;
            int m = m0 + r;
            float4 v = make_float4(0.f, 0.f, 0.f, 0.f);
            if (m < M)
                v = *reinterpret_cast<const float4*>(A + (size_t)m * K + k0 + c4 * 4);
            __half h0, l0, h1, l1, h2, l2, h3, l3;
            split2(v.x, h0, l0); split2(v.y, h1, l1);
            split2(v.z, h2, l2); split2(v.w, h3, l3);
            int base = r * S + c4 * 4;
            *reinterpret_cast<__half2*>(Ah + base)     = __halves2half2(h0, h1);
            *reinterpret_cast<__half2*>(Ah + base + 2) = __halves2half2(h2, h3);
            *reinterpret_cast<__half2*>(Al + base)     = __halves2half2(l0, l1);
            *reinterpret_cast<__half2*>(Al + base + 2) = __halves2half2(l2, l3);
        }
        // ---- W tile: 32xN fp32, transpose+split to Wh/Wl[n][k] ----
        constexpr int BTOT4 = BK * N / 4;
        #pragma unroll
        for (int i = 0; i < BTOT4 / 256; i++) {
            int idx = tid + i * 256;
            int r = idx / (N / 4), c4 = idx % (N / 4);
            float4 v = *reinterpret_cast<const float4*>(W + (size_t)(k0 + r) * N + c4 * 4);
            const float vv[4] = {v.x, v.y, v.z, v.w};
            #pragma unroll
            for (int j = 0; j < 4; j++) {
                __half hi, lo;
                split2(vv[j], hi, lo);
                int n = c4 * 4 + j;
                Wh[n * S + r] = hi;
                Wl[n * S + r] = lo;
            }
        }
        __syncthreads();

        // ---- compute: 2 chunks of k16 ----
        #pragma unroll
        for (int kk = 0; kk < BK; kk += 16) {
            unsigned ah[MT][4], al[MT][4];
            #pragma unroll
            for (int mt = 0; mt < MT; mt++) {
                int r0 = (wm + mt * 16 + g) * S + kk + tg * 2;
                int r1 = r0 + 8 * S;
                ah[mt][0] = *reinterpret_cast<const unsigned*>(Ah + r0);
                ah[mt][1] = *reinterpret_cast<const unsigned*>(Ah + r1);
                ah[mt][2] = *reinterpret_cast<const unsigned*>(Ah + r0 + 8);
                ah[mt][3] = *reinterpret_cast<const unsigned*>(Ah + r1 + 8);
                al[mt][0] = *reinterpret_cast<const unsigned*>(Al + r0);
                al[mt][1] = *reinterpret_cast<const unsigned*>(Al + r1);
                al[mt][2] = *reinterpret_cast<const unsigned*>(Al + r0 + 8);
                al[mt][3] = *reinterpret_cast<const unsigned*>(Al + r1 + 8);
            }
            #pragma unroll
            for (int nt = 0; nt < NT; nt++) {
                int nb = (wn + nt * 8 + g) * S + kk + tg * 2;
                unsigned bh[2], bl[2];
                bh[0] = *reinterpret_cast<const unsigned*>(Wh + nb);
                bh[1] = *reinterpret_cast<const unsigned*>(Wh + nb + 8);
                bl[0] = *reinterpret_cast<const unsigned*>(Wl + nb);
                bl[1] = *reinterpret_cast<const unsigned*>(Wl + nb + 8);
                #pragma unroll
                for (int mt = 0; mt < MT; mt++) {
                    mma_f16(acc[mt][nt], ah[mt], bh);
                    mma_f16(acc[mt][nt], ah[mt], bl);
                    mma_f16(acc[mt][nt], al[mt], bh);
                }
            }
        }
        __syncthreads();
    }

    // store fp16: c0,c1 at (row, 2tg), c2,c3 at (row+8, 2tg)
    #pragma unroll
    for (int mt = 0; mt < MT; mt++) {
        #pragma unroll
        for (int nt = 0; nt < NT; nt++) {
            int row0 = m0 + wm + mt * 16 + g;
            int col = wn + nt * 8 + 2 * tg;
            if (row0 < M)
                *reinterpret_cast<__half2*>(C + (size_t)row0 * N + col) =
                    __floats2half2_rn(acc[mt][nt][0], acc[mt][nt][1]);
            int row1 = row0 + 8;
            if (row1 < M)
                *reinterpret_cast<__half2*>(C + (size_t)row1 * N + col) =
                    __floats2half2_rn(acc[mt][nt][2], acc[mt][nt][3]);
        }
    }
}

// ---------------------------------------------------------------------------
// aggregation: warp per node; gathers fp16 rows, accumulates fp32
// ---------------------------------------------------------------------------
template <int VEC>
__device__ __forceinline__ void loadh(float* d, const __half* __restrict__ p) {
    if constexpr (VEC == 4) {
        uint2 raw = __ldg(reinterpret_cast<const uint2*>(p));
        float2 a = __half22float2(*reinterpret_cast<const __half2*>(&raw.x));
        float2 b = __half22float2(*reinterpret_cast<const __half2*>(&raw.y));
        d[0] = a.x; d[1] = a.y; d[2] = b.x; d[3] = b.y;
    } else if constexpr (VEC == 2) {
        __half2 h2 = __ldg(reinterpret_cast<const __half2*>(p));
        float2 a = __half22float2(h2);
        d[0] = a.x; d[1] = a.y;
    } else {
        d[0] = __half2float(__ldg(p));
    }
}

template <int F, bool RELU>
__launch_bounds__(256)
__global__ void k_agg(const __half* __restrict__ h, const float* __restrict__ bias,
                      float* __restrict__ out) {
    constexpr int VEC = F / 32;
    int node = (blockIdx.x * blockDim.x + threadIdx.x) >> 5;
    int lane = threadIdx.x & 31;
    if (node >= NN) return;

    float acc[VEC];
    {
        float d = g_dis[node];
        float ns = d * d;
        float t[VEC];
        loadh<VEC>(t, h + (size_t)node * F + lane * VEC);
        #pragma unroll
        for (int v = 0; v < VEC; v++) acc[v] = ns * t[v];
    }

    int start = g_off[node];
    int cnt   = g_cnt[node];
    int e = start, end = start + cnt;

    for (; e + 4 <= end; e += 4) {
        int   s0 = g_esrc[e],   s1 = g_esrc[e + 1],   s2 = g_esrc[e + 2],   s3 = g_esrc[e + 3];
        float n0 = g_enorm[e],  n1 = g_enorm[e + 1],  n2 = g_enorm[e + 2],  n3 = g_enorm[e + 3];
        float t0[VEC], t1[VEC], t2[VEC], t3[VEC];
        loadh<VEC>(t0, h + (size_t)s0 * F + lane * VEC);
        loadh<VEC>(t1, h + (size_t)s1 * F + lane * VEC);
        loadh<VEC>(t2, h + (size_t)s2 * F + lane * VEC);
        loadh<VEC>(t3, h + (size_t)s3 * F + lane * VEC);
        #pragma unroll
        for (int v = 0; v < VEC; v++) {
            acc[v] += n0 * t0[v];
            acc[v] += n1 * t1[v];
            acc[v] += n2 * t2[v];
            acc[v] += n3 * t3[v];
        }
    }
    for (; e < end; e++) {
        int s = g_esrc[e];
        float nm = g_enorm[e];
        float t[VEC];
        loadh<VEC>(t, h + (size_t)s * F + lane * VEC);
        #pragma unroll
        for (int v = 0; v < VEC; v++) acc[v] += nm * t[v];
    }

    float res[VEC];
    #pragma unroll
    for (int v = 0; v < VEC; v++) {
        float r = acc[v] + bias[lane * VEC + v];
        if (RELU) r = fmaxf(r, 0.0f);
        res[v] = r;
    }
    float* op = out + (size_t)node * F + lane * VEC;
    if constexpr (VEC == 4)      *reinterpret_cast<float4*>(op) = make_float4(res[0], res[1], res[2], res[3]);
    else if constexpr (VEC == 2) *reinterpret_cast<float2*>(op) = make_float2(res[0], res[1]);
    else                         *op = res[0];
}

// ---------------------------------------------------------------------------
extern "C" void kernel_launch(void* const* d_in, const int* in_sizes, int n_in,
                              void* d_out, int out_size) {
    const float* x  = (const float*)d_in[0];
    const int*   ei = (const int*)d_in[1];
    const float* W1 = (const float*)d_in[2];
    const float* b1 = (const float*)d_in[3];
    const float* W2 = (const float*)d_in[4];
    const float* b2 = (const float*)d_in[5];
    const float* W3 = (const float*)d_in[6];
    const float* b3 = (const float*)d_in[7];

    int M = in_sizes[0] / IN_C;   // 100000
    int E = in_sizes[1] / 2;      // 1600000
    const int* row = ei;          // sources
    const int* col = ei + E;      // targets
    float* out = (float*)d_out;

    __half* gh;
    float*  ga;
    cudaGetSymbolAddress((void**)&gh, g_h);
    cudaGetSymbolAddress((void**)&ga, g_a4);

    int nb1024 = (M + 1023) / 1024;

    // --- graph preprocessing: CSR by destination + symmetric norm ---
    k_zero   <<<(M + 255) / 256, 256>>>(M);
    k_count  <<<(E + 255) / 256, 256>>>(col, E);
    k_dis    <<<(M + 255) / 256, 256>>>(M);
    k_scan1  <<<nb1024, 1024>>>(M);
    k_scan2  <<<1, 32>>>(nb1024);
    k_scan3  <<<(M + 255) / 256, 256>>>(M);
    k_scatter<<<(E + 255) / 256, 256>>>(row, col, E);

    int aggBlocks = (M + 7) / 8;
    int gemmBlocks = (M + 127) / 128;

    // --- layer 1: 256 -> 128, relu ---
    k_gemm_f16<H1C, IN_C><<<gemmBlocks, 256>>>(x, W1, gh, M);
    k_agg<H1C, true><<<aggBlocks, 256>>>(gh, b1, ga);

    // --- layer 2: 128 -> 64, relu ---
    k_gemm_f16<H2C, H1C><<<gemmBlocks, 256>>>(ga, W2, gh, M);
    k_agg<H2C, true><<<aggBlocks, 256>>>(gh, b2, ga);

    // --- layer 3: 64 -> 32, no relu ---
    k_gemm_f16<OUTC, H2C><<<gemmBlocks, 256>>>(ga, W3, gh, M);
    k_agg<OUTC, false><<<aggBlocks, 256>>>(gh, b3, out);
}

// round 7
// speedup vs baseline: 1.5456x; 1.5456x over previous
#include <cuda_runtime.h>
#include <cuda_fp16.h>

// ---------------------------------------------------------------------------
// 3-layer GCN. R7: back to tf32 MMA GEMM (R6 fp16-split regressed), but
// single-pass tf32 (no 3x hi/lo split) with f32->tf32 conversion hoisted to
// the smem tile store. Inner loop = pure LDS + MMA. fp16 feature gathers in
// agg (R5 win) kept. CSR preproc kept; scatter uses pre-seeded cursors.
// ---------------------------------------------------------------------------

#define NN 100000
#define NE 1600000
#define IN_C 256
#define H1C 128
#define H2C 64
#define OUTC 32

__device__ int    g_cnt[NN];
__device__ int    g_cursor[NN];
__device__ int    g_off[NN];
__device__ int    g_bsum[128];
__device__ int    g_boff[128];
__device__ float  g_dis[NN];
__device__ int    g_esrc[NE];
__device__ float  g_enorm[NE];
__device__ __half g_h[(size_t)NN * 128];   // transformed features, fp16
__device__ float4 g_a4[(size_t)NN * 32];   // aggregated features, fp32

// ---------------------------------------------------------------------------
// graph preprocessing
// ---------------------------------------------------------------------------
__global__ void k_zero(int n) {
    int i = blockIdx.x * blockDim.x + threadIdx.x;
    if (i < n) g_cnt[i] = 0;
}

__global__ void k_count(const int* __restrict__ col, int e_cnt) {
    int e = blockIdx.x * blockDim.x + threadIdx.x;
    if (e < e_cnt) atomicAdd(&g_cnt[col[e]], 1);
}

__global__ void k_dis(int n) {
    int i = blockIdx.x * blockDim.x + threadIdx.x;
    if (i < n) g_dis[i] = rsqrtf((float)g_cnt[i] + 1.0f);
}

__global__ void k_scan1(int n) {
    __shared__ int s[1024];
    int i = blockIdx.x * 1024 + threadIdx.x;
    int v = (i < n) ? g_cnt[i] : 0;
    s[threadIdx.x] = v;
    __syncthreads();
    #pragma unroll
    for (int off = 1; off < 1024; off <<= 1) {
        int t = (threadIdx.x >= off) ? s[threadIdx.x - off] : 0;
        __syncthreads();
        s[threadIdx.x] += t;
        __syncthreads();
    }
    if (i < n) g_off[i] = s[threadIdx.x];
    if (threadIdx.x == 1023) g_bsum[blockIdx.x] = s[1023];
}

__global__ void k_scan2(int nb) {
    if (blockIdx.x == 0 && threadIdx.x == 0) {
        int run = 0;
        for (int b = 0; b < nb; b++) { g_boff[b] = run; run += g_bsum[b]; }
    }
}

__global__ void k_scan3(int n) {
    int i = blockIdx.x * blockDim.x + threadIdx.x;
    if (i < n) {
        int off = g_off[i] - g_cnt[i] + g_boff[i >> 10];  // exclusive
        g_off[i] = off;
        g_cursor[i] = off;   // scatter cursor pre-seeded to start offset
    }
}

__global__ void k_scatter(const int* __restrict__ row, const int* __restrict__ col, int e_cnt) {
    int e = blockIdx.x * blockDim.x + threadIdx.x;
    if (e >= e_cnt) return;
    int r = row[e], c = col[e];
    int pos = atomicAdd(&g_cursor[c], 1);
    g_esrc[pos]  = r;
    g_enorm[pos] = g_dis[r] * g_dis[c];
}

// ---------------------------------------------------------------------------
// single-pass tf32 GEMM: C[M,N] = A[M,K] @ W[K,N], fp16 output.
// f32 -> tf32 conversion happens once at smem store; mainloop = LDS + MMA.
// ---------------------------------------------------------------------------
__device__ __forceinline__ unsigned f2tf(float f) {
    unsigned r;
    asm("cvt.rna.tf32.f32 %0, %1;" : "=r"(r) : "f"(f));
    return r;
}

__device__ __forceinline__ void mma_tf32(float* c, const unsigned* a, const unsigned* b) {
    asm volatile(
        "mma.sync.aligned.m16n8k8.row.col.f32.tf32.tf32.f32 "
        "{%0,%1,%2,%3},{%4,%5,%6,%7},{%8,%9},{%0,%1,%2,%3};"
        : "+f"(c[0]), "+f"(c[1]), "+f"(c[2]), "+f"(c[3])
        : "r"(a[0]), "r"(a[1]), "r"(a[2]), "r"(a[3]), "r"(b[0]), "r"(b[1]));
}

template <int N, int K>
__launch_bounds__(256)
__global__ void k_gemm_tc(const float* __restrict__ A, const float* __restrict__ W,
                          __half* __restrict__ C, int M) {
    constexpr int BM = 128, BK = 32;
    constexpr int WARPS_M = 4, WARPS_N = 2;
    constexpr int WM = BM / WARPS_M;   // 32
    constexpr int WN = N / WARPS_N;    // 64 / 32 / 16
    constexpr int MT = WM / 16;        // 2
    constexpr int NT = WN / 8;         // 8 / 4 / 2
    constexpr int ASTRIDE = BK + 4;
    constexpr int BSTRIDE = N + 4;

    __shared__ unsigned As[BM * ASTRIDE];   // tf32 bits
    __shared__ unsigned Ws[BK * BSTRIDE];   // tf32 bits

    int tid = threadIdx.x;
    int lane = tid & 31, warp = tid >> 5;
    int wm = (warp % WARPS_M) * WM;
    int wn = (warp / WARPS_M) * WN;
    int m0 = blockIdx.x * BM;
    int g = lane >> 2, tg = lane & 3;

    float acc[MT][NT][4] = {};

    for (int k0 = 0; k0 < K; k0 += BK) {
        // A tile: 128x32 fp32 -> tf32 in smem
        #pragma unroll
        for (int i = 0; i < 4; i++) {
            int idx = tid + i * 256;
            int r = idx >> 3, c4 = idx & 7;
            int m = m0 + r;
            float4 v = make_float4(0.f, 0.f, 0.f, 0.f);
            if (m < M)
                v = *reinterpret_cast<const float4*>(A + (size_t)m * K + k0 + c4 * 4);
            uint4 u = make_uint4(f2tf(v.x), f2tf(v.y), f2tf(v.z), f2tf(v.w));
            *reinterpret_cast<uint4*>(As + r * ASTRIDE + c4 * 4) = u;
        }
        // W tile: 32xN fp32 -> tf32 in smem
        constexpr int BTOT4 = BK * N / 4;
        #pragma unroll
        for (int i = 0; i < BTOT4 / 256; i++) {
            int idx = tid + i * 256;
            int r = idx / (N / 4), c4 = idx % (N / 4);
            float4 v = *reinterpret_cast<const float4*>(W + (size_t)(k0 + r) * N + c4 * 4);
            uint4 u = make_uint4(f2tf(v.x), f2tf(v.y), f2tf(v.z), f2tf(v.w));
            *reinterpret_cast<uint4*>(Ws + r * BSTRIDE + c4 * 4) = u;
        }
        __syncthreads();

        #pragma unroll
        for (int kk = 0; kk < BK; kk += 8) {
            unsigned a[MT][4];
            #pragma unroll
            for (int mt = 0; mt < MT; mt++) {
                #pragma unroll
                for (int j = 0; j < 4; j++) {
                    int row = wm + mt * 16 + g + (j & 1) * 8;
                    int col = kk + tg + (j >> 1) * 4;
                    a[mt][j] = As[row * ASTRIDE + col];
                }
            }
            #pragma unroll
            for (int nt = 0; nt < NT; nt++) {
                unsigned b[2];
                #pragma unroll
                for (int j = 0; j < 2; j++) {
                    int kr = kk + tg + j * 4;
                    int col = wn + nt * 8 + g;
                    b[j] = Ws[kr * BSTRIDE + col];
                }
                #pragma unroll
                for (int mt = 0; mt < MT; mt++)
                    mma_tf32(acc[mt][nt], a[mt], b);
            }
        }
        __syncthreads();
    }

    // store fp16: c0,c1 at (row, 2tg), c2,c3 at (row+8, 2tg)
    #pragma unroll
    for (int mt = 0; mt < MT; mt++) {
        #pragma unroll
        for (int nt = 0; nt < NT; nt++) {
            int row0 = m0 + wm + mt * 16 + g;
            int col = wn + nt * 8 + 2 * tg;
            if (row0 < M)
                *reinterpret_cast<__half2*>(C + (size_t)row0 * N + col) =
                    __floats2half2_rn(acc[mt][nt][0], acc[mt][nt][1]);
            int row1 = row0 + 8;
            if (row1 < M)
                *reinterpret_cast<__half2*>(C + (size_t)row1 * N + col) =
                    __floats2half2_rn(acc[mt][nt][2], acc[mt][nt][3]);
        }
    }
}

// ---------------------------------------------------------------------------
// aggregation: warp per node; gathers fp16 rows, accumulates fp32
// ---------------------------------------------------------------------------
template <int VEC>
__device__ __forceinline__ void loadh(float* d, const __half* __restrict__ p) {
    if constexpr (VEC == 4) {
        uint2 raw = __ldg(reinterpret_cast<const uint2*>(p));
        float2 a = __half22float2(*reinterpret_cast<const __half2*>(&raw.x));
        float2 b = __half22float2(*reinterpret_cast<const __half2*>(&raw.y));
        d[0] = a.x; d[1] = a.y; d[2] = b.x; d[3] = b.y;
    } else if constexpr (VEC == 2) {
        __half2 h2 = __ldg(reinterpret_cast<const __half2*>(p));
        float2 a = __half22float2(h2);
        d[0] = a.x; d[1] = a.y;
    } else {
        d[0] = __half2float(__ldg(p));
    }
}

template <int F, bool RELU>
__launch_bounds__(256)
__global__ void k_agg(const __half* __restrict__ h, const float* __restrict__ bias,
                      float* __restrict__ out) {
    constexpr int VEC = F / 32;
    int node = (blockIdx.x * blockDim.x + threadIdx.x) >> 5;
    int lane = threadIdx.x & 31;
    if (node >= NN) return;

    float acc[VEC];
    {
        float d = g_dis[node];
        float ns = d * d;
        float t[VEC];
        loadh<VEC>(t, h + (size_t)node * F + lane * VEC);
        #pragma unroll
        for (int v = 0; v < VEC; v++) acc[v] = ns * t[v];
    }

    int start = g_off[node];
    int cnt   = g_cnt[node];
    int e = start, end = start + cnt;

    for (; e + 4 <= end; e += 4) {
        int   s0 = g_esrc[e],   s1 = g_esrc[e + 1],   s2 = g_esrc[e + 2],   s3 = g_esrc[e + 3];
        float n0 = g_enorm[e],  n1 = g_enorm[e + 1],  n2 = g_enorm[e + 2],  n3 = g_enorm[e + 3];
        float t0[VEC], t1[VEC], t2[VEC], t3[VEC];
        loadh<VEC>(t0, h + (size_t)s0 * F + lane * VEC);
        loadh<VEC>(t1, h + (size_t)s1 * F + lane * VEC);
        loadh<VEC>(t2, h + (size_t)s2 * F + lane * VEC);
        loadh<VEC>(t3, h + (size_t)s3 * F + lane * VEC);
        #pragma unroll
        for (int v = 0; v < VEC; v++) {
            acc[v] += n0 * t0[v];
            acc[v] += n1 * t1[v];
            acc[v] += n2 * t2[v];
            acc[v] += n3 * t3[v];
        }
    }
    for (; e < end; e++) {
        int s = g_esrc[e];
        float nm = g_enorm[e];
        float t[VEC];
        loadh<VEC>(t, h + (size_t)s * F + lane * VEC);
        #pragma unroll
        for (int v = 0; v < VEC; v++) acc[v] += nm * t[v];
    }

    float res[VEC];
    #pragma unroll
    for (int v = 0; v < VEC; v++) {
        float r = acc[v] + bias[lane * VEC + v];
        if (RELU) r = fmaxf(r, 0.0f);
        res[v] = r;
    }
    float* op = out + (size_t)node * F + lane * VEC;
    if constexpr (VEC == 4)      *reinterpret_cast<float4*>(op) = make_float4(res[0], res[1], res[2], res[3]);
    else if constexpr (VEC == 2) *reinterpret_cast<float2*>(op) = make_float2(res[0], res[1]);
    else                         *op = res[0];
}

// ---------------------------------------------------------------------------
extern "C" void kernel_launch(void* const* d_in, const int* in_sizes, int n_in,
                              void* d_out, int out_size) {
    const float* x  = (const float*)d_in[0];
    const int*   ei = (const int*)d_in[1];
    const float* W1 = (const float*)d_in[2];
    const float* b1 = (const float*)d_in[3];
    const float* W2 = (const float*)d_in[4];
    const float* b2 = (const float*)d_in[5];
    const float* W3 = (const float*)d_in[6];
    const float* b3 = (const float*)d_in[7];

    int M = in_sizes[0] / IN_C;   // 100000
    int E = in_sizes[1] / 2;      // 1600000
    const int* row = ei;          // sources
    const int* col = ei + E;      // targets
    float* out = (float*)d_out;

    __half* gh;
    float*  ga;
    cudaGetSymbolAddress((void**)&gh, g_h);
    cudaGetSymbolAddress((void**)&ga, g_a4);

    int nb1024 = (M + 1023) / 1024;

    // --- graph preprocessing: CSR by destination + symmetric norm ---
    k_zero   <<<(M + 255) / 256, 256>>>(M);
    k_count  <<<(E + 255) / 256, 256>>>(col, E);
    k_dis    <<<(M + 255) / 256, 256>>>(M);
    k_scan1  <<<nb1024, 1024>>>(M);
    k_scan2  <<<1, 32>>>(nb1024);
    k_scan3  <<<(M + 255) / 256, 256>>>(M);
    k_scatter<<<(E + 255) / 256, 256>>>(row, col, E);

    int aggBlocks = (M + 7) / 8;
    int gemmBlocks = (M + 127) / 128;

    // --- layer 1: 256 -> 128, relu ---
    k_gemm_tc<H1C, IN_C><<<gemmBlocks, 256>>>(x, W1, gh, M);
    k_agg<H1C, true><<<aggBlocks, 256>>>(gh, b1, ga);

    // --- layer 2: 128 -> 64, relu ---
    k_gemm_tc<H2C, H1C><<<gemmBlocks, 256>>>(ga, W2, gh, M);
    k_agg<H2C, true><<<aggBlocks, 256>>>(gh, b2, ga);

    // --- layer 3: 64 -> 32, no relu ---
    k_gemm_tc<OUTC, H2C><<<gemmBlocks, 256>>>(ga, W3, gh, M);
    k_agg<OUTC, false><<<aggBlocks, 256>>>(gh, b3, out);
}

// round 8
// speedup vs baseline: 1.5516x; 1.0039x over previous
#include <cuda_runtime.h>
#include <cuda_fp16.h>

// ---------------------------------------------------------------------------
// 3-layer GCN. R8: (1) register-buffered software pipelining in the tf32 GEMM
// (LDGs for tile k+1 issued before computing tile k), (2) agg inner loop
// unrolled to MLP-8, (3) k_dis fused into k_scan1 and gemm1 moved to launch
// slot 4 so the ncu window profiles it.
// ---------------------------------------------------------------------------

#define NN 100000
#define NE 1600000
#define IN_C 256
#define H1C 128
#define H2C 64
#define OUTC 32

__device__ int    g_cnt[NN];
__device__ int    g_cursor[NN];
__device__ int    g_off[NN];
__device__ int    g_bsum[128];
__device__ int    g_boff[128];
__device__ float  g_dis[NN];
__device__ int    g_esrc[NE];
__device__ float  g_enorm[NE];
__device__ __half g_h[(size_t)NN * 128];   // transformed features, fp16
__device__ float4 g_a4[(size_t)NN * 32];   // aggregated features, fp32

// ---------------------------------------------------------------------------
// graph preprocessing
// ---------------------------------------------------------------------------
__global__ void k_zero(int n) {
    int i = blockIdx.x * blockDim.x + threadIdx.x;
    if (i < n) g_cnt[i] = 0;
}

__global__ void k_count(const int* __restrict__ col, int e_cnt) {
    int e = blockIdx.x * blockDim.x + threadIdx.x;
    if (e < e_cnt) atomicAdd(&g_cnt[col[e]], 1);
}

// scan1 + dis fused: reads cnt anyway
__global__ void k_scan1(int n) {
    __shared__ int s[1024];
    int i = blockIdx.x * 1024 + threadIdx.x;
    int v = (i < n) ? g_cnt[i] : 0;
    if (i < n) g_dis[i] = rsqrtf((float)v + 1.0f);
    s[threadIdx.x] = v;
    __syncthreads();
    #pragma unroll
    for (int off = 1; off < 1024; off <<= 1) {
        int t = (threadIdx.x >= off) ? s[threadIdx.x - off] : 0;
        __syncthreads();
        s[threadIdx.x] += t;
        __syncthreads();
    }
    if (i < n) g_off[i] = s[threadIdx.x];
    if (threadIdx.x == 1023) g_bsum[blockIdx.x] = s[1023];
}

__global__ void k_scan2(int nb) {
    if (blockIdx.x == 0 && threadIdx.x == 0) {
        int run = 0;
        for (int b = 0; b < nb; b++) { g_boff[b] = run; run += g_bsum[b]; }
    }
}

__global__ void k_scan3(int n) {
    int i = blockIdx.x * blockDim.x + threadIdx.x;
    if (i < n) {
        int off = g_off[i] - g_cnt[i] + g_boff[i >> 10];  // exclusive
        g_off[i] = off;
        g_cursor[i] = off;
    }
}

__global__ void k_scatter(const int* __restrict__ row, const int* __restrict__ col, int e_cnt) {
    int e = blockIdx.x * blockDim.x + threadIdx.x;
    if (e >= e_cnt) return;
    int r = row[e], c = col[e];
    int pos = atomicAdd(&g_cursor[c], 1);
    g_esrc[pos]  = r;
    g_enorm[pos] = g_dis[r] * g_dis[c];
}

// ---------------------------------------------------------------------------
// single-pass tf32 GEMM, software-pipelined:  C = A @ W, fp16 output
// ---------------------------------------------------------------------------
__device__ __forceinline__ unsigned f2tf(float f) {
    unsigned r;
    asm("cvt.rna.tf32.f32 %0, %1;" : "=r"(r) : "f"(f));
    return r;
}

__device__ __forceinline__ void mma_tf32(float* c, const unsigned* a, const unsigned* b) {
    asm volatile(
        "mma.sync.aligned.m16n8k8.row.col.f32.tf32.tf32.f32 "
        "{%0,%1,%2,%3},{%4,%5,%6,%7},{%8,%9},{%0,%1,%2,%3};"
        : "+f"(c[0]), "+f"(c[1]), "+f"(c[2]), "+f"(c[3])
        : "r"(a[0]), "r"(a[1]), "r"(a[2]), "r"(a[3]), "r"(b[0]), "r"(b[1]));
}

template <int N, int K>
__launch_bounds__(256)
__global__ void k_gemm_tc(const float* __restrict__ A, const float* __restrict__ W,
                          __half* __restrict__ C, int M) {
    constexpr int BM = 128, BK = 32;
    constexpr int WARPS_M = 4, WARPS_N = 2;
    constexpr int WM = BM / WARPS_M;   // 32
    constexpr int WN = N / WARPS_N;    // 64 / 32 / 16
    constexpr int MT = WM / 16;        // 2
    constexpr int NT = WN / 8;         // 8 / 4 / 2
    constexpr int ASTRIDE = BK + 4;
    constexpr int BSTRIDE = N + 4;
    constexpr int WREG = (BK * N / 4) / 256;   // float4s of W per thread

    __shared__ unsigned As[BM * ASTRIDE];
    __shared__ unsigned Ws[BK * BSTRIDE];

    int tid = threadIdx.x;
    int lane = tid & 31, warp = tid >> 5;
    int wm = (warp % WARPS_M) * WM;
    int wn = (warp / WARPS_M) * WN;
    int m0 = blockIdx.x * BM;
    int g = lane >> 2, tg = lane & 3;

    float acc[MT][NT][4] = {};
    float4 aReg[4];
    float4 wReg[WREG];

    // addressing (constant across tiles)
    int a_r[4], a_c4[4];
    #pragma unroll
    for (int i = 0; i < 4; i++) {
        int idx = tid + i * 256;
        a_r[i] = idx >> 3;
        a_c4[i] = idx & 7;
    }
    int w_r[WREG], w_c4[WREG];
    #pragma unroll
    for (int i = 0; i < WREG; i++) {
        int idx = tid + i * 256;
        w_r[i] = idx / (N / 4);
        w_c4[i] = idx % (N / 4);
    }

    // prefetch tile 0
    #pragma unroll
    for (int i = 0; i < 4; i++) {
        int m = m0 + a_r[i];
        aReg[i] = make_float4(0.f, 0.f, 0.f, 0.f);
        if (m < M)
            aReg[i] = *reinterpret_cast<const float4*>(A + (size_t)m * K + a_c4[i] * 4);
    }
    #pragma unroll
    for (int i = 0; i < WREG; i++)
        wReg[i] = *reinterpret_cast<const float4*>(W + (size_t)w_r[i] * N + w_c4[i] * 4);

    for (int k0 = 0; k0 < K; k0 += BK) {
        // commit prefetched regs -> smem (cvt once here)
        #pragma unroll
        for (int i = 0; i < 4; i++) {
            uint4 u = make_uint4(f2tf(aReg[i].x), f2tf(aReg[i].y),
                                 f2tf(aReg[i].z), f2tf(aReg[i].w));
            *reinterpret_cast<uint4*>(As + a_r[i] * ASTRIDE + a_c4[i] * 4) = u;
        }
        #pragma unroll
        for (int i = 0; i < WREG; i++) {
            uint4 u = make_uint4(f2tf(wReg[i].x), f2tf(wReg[i].y),
                                 f2tf(wReg[i].z), f2tf(wReg[i].w));
            *reinterpret_cast<uint4*>(Ws + w_r[i] * BSTRIDE + w_c4[i] * 4) = u;
        }
        __syncthreads();

        // issue next tile's LDGs (fly under the MMA work)
        int kn = k0 + BK;
        if (kn < K) {
            #pragma unroll
            for (int i = 0; i < 4; i++) {
                int m = m0 + a_r[i];
                aReg[i] = make_float4(0.f, 0.f, 0.f, 0.f);
                if (m < M)
                    aReg[i] = *reinterpret_cast<const float4*>(A + (size_t)m * K + kn + a_c4[i] * 4);
            }
            #pragma unroll
            for (int i = 0; i < WREG; i++)
                wReg[i] = *reinterpret_cast<const float4*>(W + (size_t)(kn + w_r[i]) * N + w_c4[i] * 4);
        }

        // compute on current smem tile
        #pragma unroll
        for (int kk = 0; kk < BK; kk += 8) {
            unsigned a[MT][4];
            #pragma unroll
            for (int mt = 0; mt < MT; mt++) {
                #pragma unroll
                for (int j = 0; j < 4; j++) {
                    int row = wm + mt * 16 + g + (j & 1) * 8;
                    int col = kk + tg + (j >> 1) * 4;
                    a[mt][j] = As[row * ASTRIDE + col];
                }
            }
            #pragma unroll
            for (int nt = 0; nt < NT; nt++) {
                unsigned b[2];
                #pragma unroll
                for (int j = 0; j < 2; j++) {
                    int kr = kk + tg + j * 4;
                    int col = wn + nt * 8 + g;
                    b[j] = Ws[kr * BSTRIDE + col];
                }
                #pragma unroll
                for (int mt = 0; mt < MT; mt++)
                    mma_tf32(acc[mt][nt], a[mt], b);
            }
        }
        __syncthreads();
    }

    #pragma unroll
    for (int mt = 0; mt < MT; mt++) {
        #pragma unroll
        for (int nt = 0; nt < NT; nt++) {
            int row0 = m0 + wm + mt * 16 + g;
            int col = wn + nt * 8 + 2 * tg;
            if (row0 < M)
                *reinterpret_cast<__half2*>(C + (size_t)row0 * N + col) =
                    __floats2half2_rn(acc[mt][nt][0], acc[mt][nt][1]);
            int row1 = row0 + 8;
            if (row1 < M)
                *reinterpret_cast<__half2*>(C + (size_t)row1 * N + col) =
                    __floats2half2_rn(acc[mt][nt][2], acc[mt][nt][3]);
        }
    }
}

// ---------------------------------------------------------------------------
// aggregation: warp per node; fp16 gathers, fp32 accumulate, MLP-8 unroll
// ---------------------------------------------------------------------------
template <int VEC>
__device__ __forceinline__ void loadh(float* d, const __half* __restrict__ p) {
    if constexpr (VEC == 4) {
        uint2 raw = __ldg(reinterpret_cast<const uint2*>(p));
        float2 a = __half22float2(*reinterpret_cast<const __half2*>(&raw.x));
        float2 b = __half22float2(*reinterpret_cast<const __half2*>(&raw.y));
        d[0] = a.x; d[1] = a.y; d[2] = b.x; d[3] = b.y;
    } else if constexpr (VEC == 2) {
        __half2 h2 = __ldg(reinterpret_cast<const __half2*>(p));
        float2 a = __half22float2(h2);
        d[0] = a.x; d[1] = a.y;
    } else {
        d[0] = __half2float(__ldg(p));
    }
}

template <int F, bool RELU>
__launch_bounds__(256)
__global__ void k_agg(const __half* __restrict__ h, const float* __restrict__ bias,
                      float* __restrict__ out) {
    constexpr int VEC = F / 32;
    int node = (blockIdx.x * blockDim.x + threadIdx.x) >> 5;
    int lane = threadIdx.x & 31;
    if (node >= NN) return;

    float acc[VEC];
    {
        float d = g_dis[node];
        float ns = d * d;
        float t[VEC];
        loadh<VEC>(t, h + (size_t)node * F + lane * VEC);
        #pragma unroll
        for (int v = 0; v < VEC; v++) acc[v] = ns * t[v];
    }

    int start = g_off[node];
    int cnt   = g_cnt[node];
    int e = start, end = start + cnt;

    for (; e + 8 <= end; e += 8) {
        int   s[8];
        float nm[8];
        #pragma unroll
        for (int j = 0; j < 8; j++) { s[j] = g_esrc[e + j]; nm[j] = g_enorm[e + j]; }
        float t[8][VEC];
        #pragma unroll
        for (int j = 0; j < 8; j++)
            loadh<VEC>(t[j], h + (size_t)s[j] * F + lane * VEC);
        #pragma unroll
        for (int j = 0; j < 8; j++)
            #pragma unroll
            for (int v = 0; v < VEC; v++) acc[v] += nm[j] * t[j][v];
    }
    for (; e + 4 <= end; e += 4) {
        int   s[4];
        float nm[4];
        #pragma unroll
        for (int j = 0; j < 4; j++) { s[j] = g_esrc[e + j]; nm[j] = g_enorm[e + j]; }
        float t[4][VEC];
        #pragma unroll
        for (int j = 0; j < 4; j++)
            loadh<VEC>(t[j], h + (size_t)s[j] * F + lane * VEC);
        #pragma unroll
        for (int j = 0; j < 4; j++)
            #pragma unroll
            for (int v = 0; v < VEC; v++) acc[v] += nm[j] * t[j][v];
    }
    for (; e < end; e++) {
        int s0 = g_esrc[e];
        float nm = g_enorm[e];
        float t[VEC];
        loadh<VEC>(t, h + (size_t)s0 * F + lane * VEC);
        #pragma unroll
        for (int v = 0; v < VEC; v++) acc[v] += nm * t[v];
    }

    float res[VEC];
    #pragma unroll
    for (int v = 0; v < VEC; v++) {
        float r = acc[v] + bias[lane * VEC + v];
        if (RELU) r = fmaxf(r, 0.0f);
        res[v] = r;
    }
    float* op = out + (size_t)node * F + lane * VEC;
    if constexpr (VEC == 4)      *reinterpret_cast<float4*>(op) = make_float4(res[0], res[1], res[2], res[3]);
    else if constexpr (VEC == 2) *reinterpret_cast<float2*>(op) = make_float2(res[0], res[1]);
    else                         *op = res[0];
}

// ---------------------------------------------------------------------------
extern "C" void kernel_launch(void* const* d_in, const int* in_sizes, int n_in,
                              void* d_out, int out_size) {
    const float* x  = (const float*)d_in[0];
    const int*   ei = (const int*)d_in[1];
    const float* W1 = (const float*)d_in[2];
    const float* b1 = (const float*)d_in[3];
    const float* W2 = (const float*)d_in[4];
    const float* b2 = (const float*)d_in[5];
    const float* W3 = (const float*)d_in[6];
    const float* b3 = (const float*)d_in[7];

    int M = in_sizes[0] / IN_C;   // 100000
    int E = in_sizes[1] / 2;      // 1600000
    const int* row = ei;          // sources
    const int* col = ei + E;      // targets
    float* out = (float*)d_out;

    __half* gh;
    float*  ga;
    cudaGetSymbolAddress((void**)&gh, g_h);
    cudaGetSymbolAddress((void**)&ga, g_a4);

    int nb1024 = (M + 1023) / 1024;
    int aggBlocks = (M + 7) / 8;
    int gemmBlocks = (M + 127) / 128;

    // launch order chosen so gemm1 sits in the ncu window (slot 4);
    // gemm1 depends only on x/W1, not on the CSR build.
    k_zero   <<<(M + 255) / 256, 256>>>(M);                       // 1
    k_count  <<<(E + 255) / 256, 256>>>(col, E);                  // 2
    k_scan1  <<<nb1024, 1024>>>(M);                               // 3 (+dis)
    k_gemm_tc<H1C, IN_C><<<gemmBlocks, 256>>>(x, W1, gh, M);      // 4 <- profiled
    k_scan2  <<<1, 32>>>(nb1024);                                 // 5
    k_scan3  <<<(M + 255) / 256, 256>>>(M);                       // 6
    k_scatter<<<(E + 255) / 256, 256>>>(row, col, E);             // 7

    // --- layer 1 agg, then layers 2,3 ---
    k_agg<H1C, true><<<aggBlocks, 256>>>(gh, b1, ga);

    k_gemm_tc<H2C, H1C><<<gemmBlocks, 256>>>(ga, W2, gh, M);
    k_agg<H2C, true><<<aggBlocks, 256>>>(gh, b2, ga);

    k_gemm_tc<OUTC, H2C><<<gemmBlocks, 256>>>(ga, W3, gh, M);
    k_agg<OUTC, false><<<aggBlocks, 256>>>(gh, b3, out);
}